// round 3
// baseline (speedup 1.0000x reference)
#include <cuda_runtime.h>
#include <cuda_bf16.h>

// Problem constants (match reference)
#define Nn 50000
#define Ee 640000
#define Hh 128
#define Gg 64
#define Oo 16

// Scratch (static __device__ — no allocs allowed)
__device__ float g_deg[Nn];
__device__ float g_dinv[Nn];
__device__ float g_xw[(size_t)Nn * Hh];
__device__ float g_h[(size_t)Nn * Hh];
__device__ float g_pool[Gg * Hh];
__device__ float g_cnt[Gg];

// ---------------- init / utility ----------------

__global__ void init_deg_kernel() {
    int i = blockIdx.x * blockDim.x + threadIdx.x;
    if (i < Nn) g_deg[i] = 1.0f;  // self-loop weight 1
}

__global__ void deg_atomic_kernel(const int* __restrict__ col,
                                  const float* __restrict__ ew) {
    int e = blockIdx.x * blockDim.x + threadIdx.x;
    if (e < Ee) atomicAdd(&g_deg[col[e]], ew[e]);
}

__global__ void dinv_kernel() {
    int i = blockIdx.x * blockDim.x + threadIdx.x;
    if (i < Nn) {
        float d = g_deg[i];
        g_dinv[i] = (d > 0.0f) ? rsqrtf(d) : 0.0f;
    }
}

__global__ void zero_h_kernel() {
    size_t i = ((size_t)blockIdx.x * blockDim.x + threadIdx.x) * 4;
    if (i < (size_t)Nn * Hh) *(float4*)(g_h + i) = make_float4(0.f, 0.f, 0.f, 0.f);
}

__global__ void zero_pool_kernel() {
    int i = blockIdx.x * blockDim.x + threadIdx.x;
    if (i < Gg * Hh) g_pool[i] = 0.0f;
    if (i < Gg) g_cnt[i] = 0.0f;
}

// ---------------- GEMM: g_xw[n,128] = A[n,128] @ W[128,128] ----------------
// A == nullptr means "read from g_h".
// BM=64, BN=128, BK=32; 256 threads; each thread computes 8 rows x 4 cols.

__global__ void gemm128_kernel(const float* __restrict__ A,
                               const float* __restrict__ W, int n) {
    __shared__ float Xs[32][64];    // [k][m] (transposed)
    __shared__ float Ws[32][128];   // [k][c]

    const float* src = A ? A : (const float*)g_h;

    const int tid = threadIdx.x;
    const int block_row = blockIdx.x * 64;
    const int cg = tid & 31;        // col group: cols cg*4 .. cg*4+3
    const int rg = tid >> 5;        // row group: rows rg*8 .. rg*8+7

    float acc[8][4];
#pragma unroll
    for (int i = 0; i < 8; i++)
#pragma unroll
        for (int j = 0; j < 4; j++) acc[i][j] = 0.0f;

    const int lr = tid >> 2;           // 0..63 row to load
    const int lk = (tid & 3) * 8;      // k offset within BK chunk

    for (int k0 = 0; k0 < 128; k0 += 32) {
        // load X tile (64 rows x 32 k), transposed into Xs[k][m]
        float4 v0, v1;
        int grow = block_row + lr;
        if (grow < n) {
            const float4* p = (const float4*)(src + (size_t)grow * 128 + k0 + lk);
            v0 = p[0];
            v1 = p[1];
        } else {
            v0 = make_float4(0.f, 0.f, 0.f, 0.f);
            v1 = v0;
        }
        Xs[lk + 0][lr] = v0.x; Xs[lk + 1][lr] = v0.y;
        Xs[lk + 2][lr] = v0.z; Xs[lk + 3][lr] = v0.w;
        Xs[lk + 4][lr] = v1.x; Xs[lk + 5][lr] = v1.y;
        Xs[lk + 6][lr] = v1.z; Xs[lk + 7][lr] = v1.w;

        // load W tile (32 k x 128 cols): 1024 float4, 4 per thread
#pragma unroll
        for (int i = 0; i < 4; i++) {
            int idx = tid + i * 256;
            int kk = idx >> 5;
            int cc = (idx & 31) * 4;
            *(float4*)&Ws[kk][cc] = *(const float4*)(W + (size_t)(k0 + kk) * 128 + cc);
        }
        __syncthreads();

#pragma unroll
        for (int k = 0; k < 32; k++) {
            float4 wf = *(float4*)&Ws[k][cg * 4];
            float4 x0 = *(float4*)&Xs[k][rg * 8];
            float4 x1 = *(float4*)&Xs[k][rg * 8 + 4];
            float xf[8] = {x0.x, x0.y, x0.z, x0.w, x1.x, x1.y, x1.z, x1.w};
#pragma unroll
            for (int i = 0; i < 8; i++) {
                acc[i][0] += xf[i] * wf.x;
                acc[i][1] += xf[i] * wf.y;
                acc[i][2] += xf[i] * wf.z;
                acc[i][3] += xf[i] * wf.w;
            }
        }
        __syncthreads();
    }

#pragma unroll
    for (int i = 0; i < 8; i++) {
        int r = block_row + rg * 8 + i;
        if (r < n)
            *(float4*)(g_xw + (size_t)r * 128 + cg * 4) =
                make_float4(acc[i][0], acc[i][1], acc[i][2], acc[i][3]);
    }
}

// ---------------- edge scatter: g_h[col] += g_xw[row] * norm ----------------
// One warp per edge; each lane handles 4 consecutive features (float4 gather,
// 4 scalar atomicAdds).

__global__ void scatter_kernel(const int* __restrict__ row,
                               const int* __restrict__ col,
                               const float* __restrict__ ew) {
    int e = blockIdx.x * 8 + (threadIdx.x >> 5);
    if (e >= Ee) return;
    int lane = threadIdx.x & 31;
    int r = row[e];
    int c = col[e];
    float nrm = g_dinv[r] * ew[e] * g_dinv[c];
    float4 v = ((const float4*)(g_xw + (size_t)r * Hh))[lane];
    float* d = g_h + (size_t)c * Hh + lane * 4;
    atomicAdd(d + 0, v.x * nrm);
    atomicAdd(d + 1, v.y * nrm);
    atomicAdd(d + 2, v.z * nrm);
    atomicAdd(d + 3, v.w * nrm);
}

// ---------------- epilogue: h = relu(h + xw*dinv^2 + b) (self-loop term) ----

__global__ void epilogue_kernel(const float* __restrict__ b) {
    int i = blockIdx.x * 8 + (threadIdx.x >> 5);
    if (i >= Nn) return;
    int lane = threadIdx.x & 31;
    float d2 = g_dinv[i];
    d2 *= d2;
    size_t off = (size_t)i * Hh + lane * 4;
    float4 hv = *(float4*)(g_h + off);
    float4 xv = *(const float4*)(g_xw + off);
    float4 bv = *(const float4*)(b + lane * 4);
    hv.x = fmaxf(fmaf(xv.x, d2, hv.x) + bv.x, 0.0f);
    hv.y = fmaxf(fmaf(xv.y, d2, hv.y) + bv.y, 0.0f);
    hv.z = fmaxf(fmaf(xv.z, d2, hv.z) + bv.z, 0.0f);
    hv.w = fmaxf(fmaf(xv.w, d2, hv.w) + bv.w, 0.0f);
    *(float4*)(g_h + off) = hv;
}

// ---------------- pooling ----------------

__global__ void pool_kernel(const int* __restrict__ batch) {
    int i = blockIdx.x * 8 + (threadIdx.x >> 5);
    if (i >= Nn) return;
    int lane = threadIdx.x & 31;
    int b = batch[i];
    float4 v = *(const float4*)(g_h + (size_t)i * Hh + lane * 4);
    float* p = g_pool + b * Hh + lane * 4;
    atomicAdd(p + 0, v.x);
    atomicAdd(p + 1, v.y);
    atomicAdd(p + 2, v.z);
    atomicAdd(p + 3, v.w);
    if (lane == 0) atomicAdd(&g_cnt[b], 1.0f);
}

// ---------------- final FC: out[G,O] = (pool/cnt) @ Wfc + bfc ----------------

__global__ void fc_kernel(float* __restrict__ out,
                          const float* __restrict__ Wfc,
                          const float* __restrict__ bfc) {
    int g = threadIdx.x >> 4;   // 0..63
    int o = threadIdx.x & 15;   // 0..15
    float inv = 1.0f / fmaxf(g_cnt[g], 1.0f);
    float acc = 0.0f;
#pragma unroll 8
    for (int k = 0; k < Hh; k++) acc += g_pool[g * Hh + k] * Wfc[k * Oo + o];
    out[g * Oo + o] = acc * inv + bfc[o];
}

// ---------------- launch ----------------

extern "C" void kernel_launch(void* const* d_in, const int* in_sizes, int n_in,
                              void* d_out, int out_size) {
    const float* x = (const float*)d_in[0];
    const int* edge_index = (const int*)d_in[1];   // int32! (JAX x64 disabled)
    const float* ew = (const float*)d_in[2];
    const int* batch = (const int*)d_in[3];        // int32!
    const float* W1 = (const float*)d_in[4];
    const float* b1 = (const float*)d_in[5];
    const float* W2 = (const float*)d_in[6];
    const float* b2 = (const float*)d_in[7];
    const float* Wfc = (const float*)d_in[8];
    const float* bfc = (const float*)d_in[9];
    float* out = (float*)d_out;

    const int* row = edge_index;        // edge_index[0]
    const int* col = edge_index + Ee;   // edge_index[1]

    // degree + normalization
    init_deg_kernel<<<(Nn + 255) / 256, 256>>>();
    deg_atomic_kernel<<<(Ee + 255) / 256, 256>>>(col, ew);
    dinv_kernel<<<(Nn + 255) / 256, 256>>>();

    const int gemm_blocks = (Nn + 63) / 64;
    const int edge_blocks = (Ee + 7) / 8;
    const int node_blocks = (Nn + 7) / 8;
    const int zero_blocks = (int)(((size_t)Nn * Hh / 4 + 255) / 256);

    // layer 1: xw = x@W1 ; h = scatter(xw) ; h = relu(h + dinv^2*xw + b1)
    gemm128_kernel<<<gemm_blocks, 256>>>(x, W1, Nn);
    zero_h_kernel<<<zero_blocks, 256>>>();
    scatter_kernel<<<edge_blocks, 256>>>(row, col, ew);
    epilogue_kernel<<<node_blocks, 256>>>(b1);

    // layer 2 (gemm reads g_h via nullptr sentinel, writes g_xw; then h reset)
    gemm128_kernel<<<gemm_blocks, 256>>>(nullptr, W2, Nn);
    zero_h_kernel<<<zero_blocks, 256>>>();
    scatter_kernel<<<edge_blocks, 256>>>(row, col, ew);
    epilogue_kernel<<<node_blocks, 256>>>(b2);

    // pooling + fc
    zero_pool_kernel<<<(Gg * Hh + 255) / 256, 256>>>();
    pool_kernel<<<node_blocks, 256>>>(batch);
    fc_kernel<<<1, Gg * Oo>>>(out, Wfc, bfc);
}

// round 4
// speedup vs baseline: 1.6873x; 1.6873x over previous
#include <cuda_runtime.h>
#include <cuda_bf16.h>

// Problem constants (match reference)
#define Nn 50000
#define Ee 640000
#define Hh 128
#define Gg 64
#define Oo 16

#define SCAN_B 512
#define SCAN_NB ((Nn + SCAN_B - 1) / SCAN_B)   // 98

// Scratch (static __device__ — no allocs allowed)
__device__ float g_deg[Nn];
__device__ float g_dinv[Nn];
__device__ float g_xw[(size_t)Nn * Hh];
__device__ float g_h[(size_t)Nn * Hh];
__device__ float g_pool[Gg * Hh];
__device__ float g_cnt[Gg];

// CSR scratch
__device__ int   g_count[Nn];
__device__ int   g_cursor[Nn];
__device__ int   g_scan[Nn];
__device__ int   g_bsum[SCAN_NB];
__device__ int   g_boff[SCAN_NB];
__device__ int   g_rowptr[Nn + 1];
__device__ int   g_csr_src[Ee];
__device__ float g_csr_coef[Ee];

// ---------------- init ----------------

__global__ void init_node_kernel() {
    int i = blockIdx.x * blockDim.x + threadIdx.x;
    if (i < Nn) {
        g_deg[i] = 1.0f;   // self-loop weight 1
        g_count[i] = 0;
        g_cursor[i] = 0;
    }
}

// histogram: weighted degree (float) + edge count (int) per destination
__global__ void deg_count_kernel(const int* __restrict__ col,
                                 const float* __restrict__ ew) {
    int e = blockIdx.x * blockDim.x + threadIdx.x;
    if (e < Ee) {
        int c = col[e];
        atomicAdd(&g_deg[c], ew[e]);
        atomicAdd(&g_count[c], 1);
    }
}

__global__ void dinv_kernel() {
    int i = blockIdx.x * blockDim.x + threadIdx.x;
    if (i < Nn) {
        float d = g_deg[i];
        g_dinv[i] = (d > 0.0f) ? rsqrtf(d) : 0.0f;
    }
}

// ---------------- scan (exclusive prefix over g_count -> g_rowptr) --------

__global__ void scan_block_kernel() {
    __shared__ int sh[SCAN_B];
    int tid = threadIdx.x;
    int i = blockIdx.x * SCAN_B + tid;
    int v = (i < Nn) ? g_count[i] : 0;
    sh[tid] = v;
    __syncthreads();
#pragma unroll
    for (int o = 1; o < SCAN_B; o <<= 1) {
        int t = (tid >= o) ? sh[tid - o] : 0;
        __syncthreads();
        sh[tid] += t;
        __syncthreads();
    }
    if (i < Nn) g_scan[i] = sh[tid];   // inclusive within block
    if (tid == SCAN_B - 1) g_bsum[blockIdx.x] = sh[tid];
}

__global__ void scan_bsum_kernel() {
    __shared__ int sh[128];
    int tid = threadIdx.x;
    int v = (tid < SCAN_NB) ? g_bsum[tid] : 0;
    sh[tid] = v;
    __syncthreads();
#pragma unroll
    for (int o = 1; o < 128; o <<= 1) {
        int t = (tid >= o) ? sh[tid - o] : 0;
        __syncthreads();
        sh[tid] += t;
        __syncthreads();
    }
    if (tid < SCAN_NB) g_boff[tid] = sh[tid] - v;  // exclusive
}

__global__ void scan_final_kernel() {
    int i = blockIdx.x * blockDim.x + threadIdx.x;
    if (i < Nn) {
        g_rowptr[i + 1] = g_scan[i] + g_boff[i / SCAN_B];
        if (i == 0) g_rowptr[0] = 0;
    }
}

// fill CSR: for each edge, place (src, coef) into dst's segment
__global__ void csr_fill_kernel(const int* __restrict__ row,
                                const int* __restrict__ col,
                                const float* __restrict__ ew) {
    int e = blockIdx.x * blockDim.x + threadIdx.x;
    if (e >= Ee) return;
    int r = row[e];
    int c = col[e];
    int p = g_rowptr[c] + atomicAdd(&g_cursor[c], 1);
    g_csr_src[p] = r;
    g_csr_coef[p] = g_dinv[r] * ew[e] * g_dinv[c];
}

// ---------------- GEMM: g_xw[n,128] = A[n,128] @ W[128,128] ----------------
// A == nullptr means "read from g_h".

__global__ void gemm128_kernel(const float* __restrict__ A,
                               const float* __restrict__ W, int n) {
    __shared__ float Xs[32][64];    // [k][m] (transposed)
    __shared__ float Ws[32][128];   // [k][c]

    const float* src = A ? A : (const float*)g_h;

    const int tid = threadIdx.x;
    const int block_row = blockIdx.x * 64;
    const int cg = tid & 31;
    const int rg = tid >> 5;

    float acc[8][4];
#pragma unroll
    for (int i = 0; i < 8; i++)
#pragma unroll
        for (int j = 0; j < 4; j++) acc[i][j] = 0.0f;

    const int lr = tid >> 2;
    const int lk = (tid & 3) * 8;

    for (int k0 = 0; k0 < 128; k0 += 32) {
        float4 v0, v1;
        int grow = block_row + lr;
        if (grow < n) {
            const float4* p = (const float4*)(src + (size_t)grow * 128 + k0 + lk);
            v0 = p[0];
            v1 = p[1];
        } else {
            v0 = make_float4(0.f, 0.f, 0.f, 0.f);
            v1 = v0;
        }
        Xs[lk + 0][lr] = v0.x; Xs[lk + 1][lr] = v0.y;
        Xs[lk + 2][lr] = v0.z; Xs[lk + 3][lr] = v0.w;
        Xs[lk + 4][lr] = v1.x; Xs[lk + 5][lr] = v1.y;
        Xs[lk + 6][lr] = v1.z; Xs[lk + 7][lr] = v1.w;

#pragma unroll
        for (int i = 0; i < 4; i++) {
            int idx = tid + i * 256;
            int kk = idx >> 5;
            int cc = (idx & 31) * 4;
            *(float4*)&Ws[kk][cc] = *(const float4*)(W + (size_t)(k0 + kk) * 128 + cc);
        }
        __syncthreads();

#pragma unroll
        for (int k = 0; k < 32; k++) {
            float4 wf = *(float4*)&Ws[k][cg * 4];
            float4 x0 = *(float4*)&Xs[k][rg * 8];
            float4 x1 = *(float4*)&Xs[k][rg * 8 + 4];
            float xf[8] = {x0.x, x0.y, x0.z, x0.w, x1.x, x1.y, x1.z, x1.w};
#pragma unroll
            for (int i = 0; i < 8; i++) {
                acc[i][0] += xf[i] * wf.x;
                acc[i][1] += xf[i] * wf.y;
                acc[i][2] += xf[i] * wf.z;
                acc[i][3] += xf[i] * wf.w;
            }
        }
        __syncthreads();
    }

#pragma unroll
    for (int i = 0; i < 8; i++) {
        int r = block_row + rg * 8 + i;
        if (r < n)
            *(float4*)(g_xw + (size_t)r * 128 + cg * 4) =
                make_float4(acc[i][0], acc[i][1], acc[i][2], acc[i][3]);
    }
}

// ---------------- gather layer 1: g_h[c] = relu(agg + dinv^2*xw[c] + b) ----
// One warp per destination node; float4 of features per lane; no atomics.

__global__ void gather1_kernel(const float* __restrict__ b) {
    int node = blockIdx.x * 8 + (threadIdx.x >> 5);
    if (node >= Nn) return;
    int lane = threadIdx.x & 31;

    int start = g_rowptr[node];
    int end = g_rowptr[node + 1];

    float di = g_dinv[node];
    float d2 = di * di;
    float4 sv = ((const float4*)(g_xw + (size_t)node * Hh))[lane];
    float4 acc = make_float4(sv.x * d2, sv.y * d2, sv.z * d2, sv.w * d2);

    int p = start;
    for (; p + 1 < end; p += 2) {
        int s0 = g_csr_src[p];
        int s1 = g_csr_src[p + 1];
        float c0 = g_csr_coef[p];
        float c1 = g_csr_coef[p + 1];
        float4 v0 = ((const float4*)(g_xw + (size_t)s0 * Hh))[lane];
        float4 v1 = ((const float4*)(g_xw + (size_t)s1 * Hh))[lane];
        acc.x += c0 * v0.x + c1 * v1.x;
        acc.y += c0 * v0.y + c1 * v1.y;
        acc.z += c0 * v0.z + c1 * v1.z;
        acc.w += c0 * v0.w + c1 * v1.w;
    }
    if (p < end) {
        int s0 = g_csr_src[p];
        float c0 = g_csr_coef[p];
        float4 v0 = ((const float4*)(g_xw + (size_t)s0 * Hh))[lane];
        acc.x += c0 * v0.x;
        acc.y += c0 * v0.y;
        acc.z += c0 * v0.z;
        acc.w += c0 * v0.w;
    }

    float4 bv = *(const float4*)(b + lane * 4);
    acc.x = fmaxf(acc.x + bv.x, 0.0f);
    acc.y = fmaxf(acc.y + bv.y, 0.0f);
    acc.z = fmaxf(acc.z + bv.z, 0.0f);
    acc.w = fmaxf(acc.w + bv.w, 0.0f);
    ((float4*)(g_h + (size_t)node * Hh))[lane] = acc;
}

// ---------------- gather layer 2 fused with pooling -----------------------
// h2 is only needed pooled: skip writing it, atomicAdd straight into g_pool.

__global__ void gather2_pool_kernel(const float* __restrict__ b,
                                    const int* __restrict__ batch) {
    int node = blockIdx.x * 8 + (threadIdx.x >> 5);
    if (node >= Nn) return;
    int lane = threadIdx.x & 31;

    int start = g_rowptr[node];
    int end = g_rowptr[node + 1];

    float di = g_dinv[node];
    float d2 = di * di;
    float4 sv = ((const float4*)(g_xw + (size_t)node * Hh))[lane];
    float4 acc = make_float4(sv.x * d2, sv.y * d2, sv.z * d2, sv.w * d2);

    int p = start;
    for (; p + 1 < end; p += 2) {
        int s0 = g_csr_src[p];
        int s1 = g_csr_src[p + 1];
        float c0 = g_csr_coef[p];
        float c1 = g_csr_coef[p + 1];
        float4 v0 = ((const float4*)(g_xw + (size_t)s0 * Hh))[lane];
        float4 v1 = ((const float4*)(g_xw + (size_t)s1 * Hh))[lane];
        acc.x += c0 * v0.x + c1 * v1.x;
        acc.y += c0 * v0.y + c1 * v1.y;
        acc.z += c0 * v0.z + c1 * v1.z;
        acc.w += c0 * v0.w + c1 * v1.w;
    }
    if (p < end) {
        int s0 = g_csr_src[p];
        float c0 = g_csr_coef[p];
        float4 v0 = ((const float4*)(g_xw + (size_t)s0 * Hh))[lane];
        acc.x += c0 * v0.x;
        acc.y += c0 * v0.y;
        acc.z += c0 * v0.z;
        acc.w += c0 * v0.w;
    }

    float4 bv = *(const float4*)(b + lane * 4);
    acc.x = fmaxf(acc.x + bv.x, 0.0f);
    acc.y = fmaxf(acc.y + bv.y, 0.0f);
    acc.z = fmaxf(acc.z + bv.z, 0.0f);
    acc.w = fmaxf(acc.w + bv.w, 0.0f);

    int bg = batch[node];
    float* pl = g_pool + bg * Hh + lane * 4;
    atomicAdd(pl + 0, acc.x);
    atomicAdd(pl + 1, acc.y);
    atomicAdd(pl + 2, acc.z);
    atomicAdd(pl + 3, acc.w);
    if (lane == 0) atomicAdd(&g_cnt[bg], 1.0f);
}

// ---------------- misc ----------------

__global__ void zero_pool_kernel() {
    int i = blockIdx.x * blockDim.x + threadIdx.x;
    if (i < Gg * Hh) g_pool[i] = 0.0f;
    if (i < Gg) g_cnt[i] = 0.0f;
}

__global__ void fc_kernel(float* __restrict__ out,
                          const float* __restrict__ Wfc,
                          const float* __restrict__ bfc) {
    int g = threadIdx.x >> 4;
    int o = threadIdx.x & 15;
    float inv = 1.0f / fmaxf(g_cnt[g], 1.0f);
    float acc = 0.0f;
#pragma unroll 8
    for (int k = 0; k < Hh; k++) acc += g_pool[g * Hh + k] * Wfc[k * Oo + o];
    out[g * Oo + o] = acc * inv + bfc[o];
}

// ---------------- launch ----------------

extern "C" void kernel_launch(void* const* d_in, const int* in_sizes, int n_in,
                              void* d_out, int out_size) {
    const float* x = (const float*)d_in[0];
    const int* edge_index = (const int*)d_in[1];   // int32
    const float* ew = (const float*)d_in[2];
    const int* batch = (const int*)d_in[3];        // int32
    const float* W1 = (const float*)d_in[4];
    const float* b1 = (const float*)d_in[5];
    const float* W2 = (const float*)d_in[6];
    const float* b2 = (const float*)d_in[7];
    const float* Wfc = (const float*)d_in[8];
    const float* bfc = (const float*)d_in[9];
    float* out = (float*)d_out;

    const int* row = edge_index;        // edge_index[0]
    const int* col = edge_index + Ee;   // edge_index[1]

    const int nblk = (Nn + 255) / 256;
    const int eblk = (Ee + 255) / 256;
    const int gemm_blocks = (Nn + 63) / 64;
    const int warp8_blocks = (Nn + 7) / 8;

    // degree + CSR build
    init_node_kernel<<<nblk, 256>>>();
    deg_count_kernel<<<eblk, 256>>>(col, ew);
    dinv_kernel<<<nblk, 256>>>();
    scan_block_kernel<<<SCAN_NB, SCAN_B>>>();
    scan_bsum_kernel<<<1, 128>>>();
    scan_final_kernel<<<nblk, 256>>>();
    csr_fill_kernel<<<eblk, 256>>>(row, col, ew);

    // layer 1: xw = x@W1 ; h = relu(gather(xw) + dinv^2*xw + b1)
    gemm128_kernel<<<gemm_blocks, 256>>>(x, W1, Nn);
    gather1_kernel<<<warp8_blocks, 256>>>(b1);

    // layer 2: xw = h@W2 ; pooled gather (no h2 materialization)
    gemm128_kernel<<<gemm_blocks, 256>>>(nullptr, W2, Nn);
    zero_pool_kernel<<<(Gg * Hh + 255) / 256, 256>>>();
    gather2_pool_kernel<<<warp8_blocks, 256>>>(b2, batch);

    // fc
    fc_kernel<<<1, Gg * Oo>>>(out, Wfc, bfc);
}

// round 5
// speedup vs baseline: 2.0343x; 1.2057x over previous
#include <cuda_runtime.h>
#include <cuda_bf16.h>

// Problem constants (match reference)
#define Nn 50000
#define Ee 640000
#define Hh 128
#define Gg 64
#define Oo 16

#define SCAN_B 512
#define SCAN_NB ((Nn + SCAN_B - 1) / SCAN_B)   // 98

// Scratch (static __device__ — no allocs allowed)
__device__ float g_deg[Nn];
__device__ float g_dinv[Nn];
__device__ float g_xw[(size_t)Nn * Hh];
__device__ float g_h[(size_t)Nn * Hh];
__device__ float g_pool[Gg * Hh];
__device__ float g_cnt[Gg];

// CSR scratch
__device__ int    g_count[Nn];
__device__ int    g_cursor[Nn];
__device__ int    g_scan[Nn];
__device__ int    g_bsum[SCAN_NB];
__device__ int    g_boff[SCAN_NB];
__device__ int    g_rowptr[Nn + 1];
__device__ float2 g_csr[Ee];        // .x = src index (int bits), .y = coef

// ---------------- init ----------------

__global__ void init_node_kernel() {
    int i = blockIdx.x * blockDim.x + threadIdx.x;
    if (i < Nn) {
        g_deg[i] = 1.0f;   // self-loop weight 1
        g_count[i] = 0;
        g_cursor[i] = 0;
    }
    if (i < Gg * Hh) g_pool[i] = 0.0f;
    if (i < Gg) g_cnt[i] = 0.0f;
}

// histogram: weighted degree (float) + edge count (int) per destination
__global__ void deg_count_kernel(const int* __restrict__ col,
                                 const float* __restrict__ ew) {
    int e = blockIdx.x * blockDim.x + threadIdx.x;
    if (e < Ee) {
        int c = col[e];
        atomicAdd(&g_deg[c], ew[e]);
        atomicAdd(&g_count[c], 1);
    }
}

__global__ void dinv_kernel() {
    int i = blockIdx.x * blockDim.x + threadIdx.x;
    if (i < Nn) {
        float d = g_deg[i];
        g_dinv[i] = (d > 0.0f) ? rsqrtf(d) : 0.0f;
    }
}

// ---------------- scan (exclusive prefix over g_count -> g_rowptr) --------

__global__ void scan_block_kernel() {
    __shared__ int sh[SCAN_B];
    int tid = threadIdx.x;
    int i = blockIdx.x * SCAN_B + tid;
    int v = (i < Nn) ? g_count[i] : 0;
    sh[tid] = v;
    __syncthreads();
#pragma unroll
    for (int o = 1; o < SCAN_B; o <<= 1) {
        int t = (tid >= o) ? sh[tid - o] : 0;
        __syncthreads();
        sh[tid] += t;
        __syncthreads();
    }
    if (i < Nn) g_scan[i] = sh[tid];   // inclusive within block
    if (tid == SCAN_B - 1) g_bsum[blockIdx.x] = sh[tid];
}

__global__ void scan_bsum_kernel() {
    __shared__ int sh[128];
    int tid = threadIdx.x;
    int v = (tid < SCAN_NB) ? g_bsum[tid] : 0;
    sh[tid] = v;
    __syncthreads();
#pragma unroll
    for (int o = 1; o < 128; o <<= 1) {
        int t = (tid >= o) ? sh[tid - o] : 0;
        __syncthreads();
        sh[tid] += t;
        __syncthreads();
    }
    if (tid < SCAN_NB) g_boff[tid] = sh[tid] - v;  // exclusive
}

__global__ void scan_final_kernel() {
    int i = blockIdx.x * blockDim.x + threadIdx.x;
    if (i < Nn) {
        g_rowptr[i + 1] = g_scan[i] + g_boff[i / SCAN_B];
        if (i == 0) g_rowptr[0] = 0;
    }
}

// fill CSR: for each edge, place packed (src, coef) into dst's segment
__global__ void csr_fill_kernel(const int* __restrict__ row,
                                const int* __restrict__ col,
                                const float* __restrict__ ew) {
    int e = blockIdx.x * blockDim.x + threadIdx.x;
    if (e >= Ee) return;
    int r = row[e];
    int c = col[e];
    int p = g_rowptr[c] + atomicAdd(&g_cursor[c], 1);
    g_csr[p] = make_float2(__int_as_float(r), g_dinv[r] * ew[e] * g_dinv[c]);
}

// ---------------- GEMM: g_xw[n,128] = A[n,128] @ W[128,128] ----------------
// A == nullptr means "read from g_h". (proven kernel, unchanged)

__global__ void gemm128_kernel(const float* __restrict__ A,
                               const float* __restrict__ W, int n) {
    __shared__ float Xs[32][64];    // [k][m] (transposed)
    __shared__ float Ws[32][128];   // [k][c]

    const float* src = A ? A : (const float*)g_h;

    const int tid = threadIdx.x;
    const int block_row = blockIdx.x * 64;
    const int cg = tid & 31;
    const int rg = tid >> 5;

    float acc[8][4];
#pragma unroll
    for (int i = 0; i < 8; i++)
#pragma unroll
        for (int j = 0; j < 4; j++) acc[i][j] = 0.0f;

    const int lr = tid >> 2;
    const int lk = (tid & 3) * 8;

    for (int k0 = 0; k0 < 128; k0 += 32) {
        float4 v0, v1;
        int grow = block_row + lr;
        if (grow < n) {
            const float4* p = (const float4*)(src + (size_t)grow * 128 + k0 + lk);
            v0 = p[0];
            v1 = p[1];
        } else {
            v0 = make_float4(0.f, 0.f, 0.f, 0.f);
            v1 = v0;
        }
        Xs[lk + 0][lr] = v0.x; Xs[lk + 1][lr] = v0.y;
        Xs[lk + 2][lr] = v0.z; Xs[lk + 3][lr] = v0.w;
        Xs[lk + 4][lr] = v1.x; Xs[lk + 5][lr] = v1.y;
        Xs[lk + 6][lr] = v1.z; Xs[lk + 7][lr] = v1.w;

#pragma unroll
        for (int i = 0; i < 4; i++) {
            int idx = tid + i * 256;
            int kk = idx >> 5;
            int cc = (idx & 31) * 4;
            *(float4*)&Ws[kk][cc] = *(const float4*)(W + (size_t)(k0 + kk) * 128 + cc);
        }
        __syncthreads();

#pragma unroll
        for (int k = 0; k < 32; k++) {
            float4 wf = *(float4*)&Ws[k][cg * 4];
            float4 x0 = *(float4*)&Xs[k][rg * 8];
            float4 x1 = *(float4*)&Xs[k][rg * 8 + 4];
            float xf[8] = {x0.x, x0.y, x0.z, x0.w, x1.x, x1.y, x1.z, x1.w};
#pragma unroll
            for (int i = 0; i < 8; i++) {
                acc[i][0] += xf[i] * wf.x;
                acc[i][1] += xf[i] * wf.y;
                acc[i][2] += xf[i] * wf.z;
                acc[i][3] += xf[i] * wf.w;
            }
        }
        __syncthreads();
    }

#pragma unroll
    for (int i = 0; i < 8; i++) {
        int r = block_row + rg * 8 + i;
        if (r < n)
            *(float4*)(g_xw + (size_t)r * 128 + cg * 4) =
                make_float4(acc[i][0], acc[i][1], acc[i][2], acc[i][3]);
    }
}

// ---------------- gather core (unroll x4, packed CSR) ----------------------

__device__ __forceinline__ float4 gather_node(int node, int lane,
                                              const float* __restrict__ b) {
    int p = g_rowptr[node];
    const int end = g_rowptr[node + 1];

    float di = g_dinv[node];
    float d2 = di * di;
    float4 sv = ((const float4*)(g_xw + (size_t)node * Hh))[lane];
    float ax = sv.x * d2, ay = sv.y * d2, az = sv.z * d2, aw = sv.w * d2;

#pragma unroll 1
    for (; p + 3 < end; p += 4) {
        // issue all 4 index loads first (independent), then 4 row gathers
        float2 e0 = g_csr[p];
        float2 e1 = g_csr[p + 1];
        float2 e2 = g_csr[p + 2];
        float2 e3 = g_csr[p + 3];
        float4 v0 = ((const float4*)(g_xw + (size_t)__float_as_int(e0.x) * Hh))[lane];
        float4 v1 = ((const float4*)(g_xw + (size_t)__float_as_int(e1.x) * Hh))[lane];
        float4 v2 = ((const float4*)(g_xw + (size_t)__float_as_int(e2.x) * Hh))[lane];
        float4 v3 = ((const float4*)(g_xw + (size_t)__float_as_int(e3.x) * Hh))[lane];
        ax += e0.y * v0.x + e1.y * v1.x + e2.y * v2.x + e3.y * v3.x;
        ay += e0.y * v0.y + e1.y * v1.y + e2.y * v2.y + e3.y * v3.y;
        az += e0.y * v0.z + e1.y * v1.z + e2.y * v2.z + e3.y * v3.z;
        aw += e0.y * v0.w + e1.y * v1.w + e2.y * v2.w + e3.y * v3.w;
    }
#pragma unroll 1
    for (; p < end; p++) {
        float2 e0 = g_csr[p];
        float4 v0 = ((const float4*)(g_xw + (size_t)__float_as_int(e0.x) * Hh))[lane];
        ax += e0.y * v0.x;
        ay += e0.y * v0.y;
        az += e0.y * v0.z;
        aw += e0.y * v0.w;
    }

    float4 bv = *(const float4*)(b + lane * 4);
    return make_float4(fmaxf(ax + bv.x, 0.0f), fmaxf(ay + bv.y, 0.0f),
                       fmaxf(az + bv.z, 0.0f), fmaxf(aw + bv.w, 0.0f));
}

// layer 1: g_h[node] = relu(agg + dinv^2*xw + b1)
__global__ void gather1_kernel(const float* __restrict__ b) {
    int node = blockIdx.x * 8 + (threadIdx.x >> 5);
    if (node >= Nn) return;
    int lane = threadIdx.x & 31;
    float4 acc = gather_node(node, lane, b);
    ((float4*)(g_h + (size_t)node * Hh))[lane] = acc;
}

// layer 2 fused with pooling: h2 never materialized
__global__ void gather2_pool_kernel(const float* __restrict__ b,
                                    const int* __restrict__ batch) {
    int node = blockIdx.x * 8 + (threadIdx.x >> 5);
    if (node >= Nn) return;
    int lane = threadIdx.x & 31;
    float4 acc = gather_node(node, lane, b);
    int bg = batch[node];
    float* pl = g_pool + bg * Hh + lane * 4;
    atomicAdd(pl + 0, acc.x);
    atomicAdd(pl + 1, acc.y);
    atomicAdd(pl + 2, acc.z);
    atomicAdd(pl + 3, acc.w);
    if (lane == 0) atomicAdd(&g_cnt[bg], 1.0f);
}

// ---------------- final FC ----------------

__global__ void fc_kernel(float* __restrict__ out,
                          const float* __restrict__ Wfc,
                          const float* __restrict__ bfc) {
    int g = threadIdx.x >> 4;
    int o = threadIdx.x & 15;
    float inv = 1.0f / fmaxf(g_cnt[g], 1.0f);
    float acc = 0.0f;
#pragma unroll 8
    for (int k = 0; k < Hh; k++) acc += g_pool[g * Hh + k] * Wfc[k * Oo + o];
    out[g * Oo + o] = acc * inv + bfc[o];
}

// ---------------- launch ----------------

extern "C" void kernel_launch(void* const* d_in, const int* in_sizes, int n_in,
                              void* d_out, int out_size) {
    const float* x = (const float*)d_in[0];
    const int* edge_index = (const int*)d_in[1];   // int32
    const float* ew = (const float*)d_in[2];
    const int* batch = (const int*)d_in[3];        // int32
    const float* W1 = (const float*)d_in[4];
    const float* b1 = (const float*)d_in[5];
    const float* W2 = (const float*)d_in[6];
    const float* b2 = (const float*)d_in[7];
    const float* Wfc = (const float*)d_in[8];
    const float* bfc = (const float*)d_in[9];
    float* out = (float*)d_out;

    const int* row = edge_index;        // edge_index[0]
    const int* col = edge_index + Ee;   // edge_index[1]

    const int nblk = (Nn + 255) / 256;
    const int eblk = (Ee + 255) / 256;
    const int gemm_blocks = (Nn + 63) / 64;
    const int warp8_blocks = (Nn + 7) / 8;

    // degree + CSR build
    init_node_kernel<<<nblk, 256>>>();
    deg_count_kernel<<<eblk, 256>>>(col, ew);
    dinv_kernel<<<nblk, 256>>>();
    scan_block_kernel<<<SCAN_NB, SCAN_B>>>();
    scan_bsum_kernel<<<1, 128>>>();
    scan_final_kernel<<<nblk, 256>>>();
    csr_fill_kernel<<<eblk, 256>>>(row, col, ew);

    // layer 1: xw = x@W1 ; h = relu(gather(xw) + dinv^2*xw + b1)
    gemm128_kernel<<<gemm_blocks, 256>>>(x, W1, Nn);
    gather1_kernel<<<warp8_blocks, 256>>>(b1);

    // layer 2: xw = h@W2 ; pooled gather (no h2 materialization)
    gemm128_kernel<<<gemm_blocks, 256>>>(nullptr, W2, Nn);
    gather2_pool_kernel<<<warp8_blocks, 256>>>(b2, batch);

    // fc
    fc_kernel<<<1, Gg * Oo>>>(out, Wfc, bfc);
}